// round 15
// baseline (speedup 1.0000x reference)
#include <cuda_runtime.h>
#include <cuda_bf16.h>
#include <cuda_fp16.h>
#include <cstdint>

#define B 16
#define N 4096
#define C 64
#define P 1024      // NPOINT
#define S 32        // NSAMPLE
#define CIN0 67
#define C1 64
#define C2 64
#define C3 128
#define CNT (B*P*S) // 524288 samples per channel for BN

#define OFF_NEWXYZ 0
#define OFF_NEWPTS (B*P*3)                 // 49152
#define OFF_IDX    (B*P*3 + B*P*C3)        // 2146304

typedef unsigned long long ull;

// ---------------- f32x2 packed helpers (exact per-lane .rn ops) --------------
__device__ __forceinline__ ull pk2(float x) {
    ull r; asm("mov.b64 %0, {%1, %1};" : "=l"(r) : "f"(x)); return r;
}
__device__ __forceinline__ ull pack2(float lo, float hi) {
    ull r; asm("mov.b64 %0, {%1, %2};" : "=l"(r) : "f"(lo), "f"(hi)); return r;
}
__device__ __forceinline__ ull mul2(ull a, ull b) {
    ull d; asm("mul.rn.f32x2 %0, %1, %2;" : "=l"(d) : "l"(a), "l"(b)); return d;
}
__device__ __forceinline__ ull add2(ull a, ull b) {
    ull d; asm("add.rn.f32x2 %0, %1, %2;" : "=l"(d) : "l"(a), "l"(b)); return d;
}
__device__ __forceinline__ void upk(ull a, float& lo, float& hi) {
    asm("mov.b64 {%0, %1}, %2;" : "=f"(lo), "=f"(hi) : "l"(a));
}

// ---------------- mma.sync bf16 (baseline sm_80+ PTX, works on sm_103) -------
__device__ __forceinline__ void mma_bf16(float* d, const uint32_t* a, uint32_t b0, uint32_t b1) {
    asm volatile("mma.sync.aligned.m16n8k16.row.col.f32.bf16.bf16.f32 "
        "{%0,%1,%2,%3}, {%4,%5,%6,%7}, {%8,%9}, {%0,%1,%2,%3};"
        : "+f"(d[0]), "+f"(d[1]), "+f"(d[2]), "+f"(d[3])
        : "r"(a[0]), "r"(a[1]), "r"(a[2]), "r"(a[3]), "r"(b0), "r"(b1));
}

// ldmatrix x4: loads a full m16k16 bf16 A tile (4 m8n8 matrices) in one instr
__device__ __forceinline__ void ldsm4(uint32_t* r, uint32_t saddr) {
    asm volatile("ldmatrix.sync.aligned.m8n8.x4.shared.b16 {%0,%1,%2,%3}, [%4];"
        : "=r"(r[0]), "=r"(r[1]), "=r"(r[2]), "=r"(r[3]) : "r"(saddr));
}

__device__ __forceinline__ uint32_t smem_u32(const void* p) {
    uint32_t a;
    asm("{ .reg .u64 t; cvta.to.shared.u64 t, %1; cvt.u32.u64 %0, t; }" : "=r"(a) : "l"(p));
    return a;
}

// split fp32 pair into bf16x2 (hi) and bf16x2 (residual lo); first arg = low half
__device__ __forceinline__ void split2(float a, float b, uint32_t& hi, uint32_t& lo) {
    __nv_bfloat16 ha = __float2bfloat16_rn(a);
    __nv_bfloat16 hb = __float2bfloat16_rn(b);
    __nv_bfloat162 hh = __halves2bfloat162(ha, hb);
    hi = *reinterpret_cast<uint32_t*>(&hh);
    float la = a - __bfloat162float(ha);
    float lb = b - __bfloat162float(hb);
    __nv_bfloat162 ll = __floats2bfloat162_rn(la, lb);
    lo = *reinterpret_cast<uint32_t*>(&ll);
}

// pack 4 floats -> 2 half2 (uint2); unpack back
__device__ __forceinline__ uint2 pack_h4(float a, float b, float c, float d) {
    __half2 p0 = __floats2half2_rn(a, b);
    __half2 p1 = __floats2half2_rn(c, d);
    uint2 r;
    r.x = *reinterpret_cast<uint32_t*>(&p0);
    r.y = *reinterpret_cast<uint32_t*>(&p1);
    return r;
}
__device__ __forceinline__ void unpack_h4(uint2 v, float& a, float& b, float& c, float& d) {
    __half2 p0 = *reinterpret_cast<__half2*>(&v.x);
    __half2 p1 = *reinterpret_cast<__half2*>(&v.y);
    float2 f0 = __half22float2(p0);
    float2 f1 = __half22float2(p1);
    a = f0.x; b = f0.y; c = f1.x; d = f1.y;
}

// ---------------- scratch (static device memory; no allocations) ------------
__device__ float g_new_xyz[B*P*3];
__device__ int   g_idx[B*P*S];
// y1/y2 in MMA FRAGMENT layout, fp16-packed: per group, 16 tiles (mt*8+nt),
// each tile = 32 lanes x uint2 {h2(c0,c1), h2(c2,c3)}. index: g*512 + tile*32 + lane
__device__ uint2 g_y1h[(size_t)B*P*512];   // 67 MB
__device__ uint2 g_y2h[(size_t)B*P*512];   // 67 MB
__device__ float g_max3[(size_t)B*P*C3];   // 8 MB

__device__ float g_sum0[C1], g_sq0[C1];
__device__ float g_sum1[C2], g_sq1[C2];
__device__ float g_sum2[C3], g_sq2[C3];

// paired pre-split weight tables: entry {hi_cb, lo_cb, hi_cb+4, lo_cb+4}
// index: (ks*4 + q)*Cout + n  where cb = 8*ks + q
__device__ uint4 g_w0q[5*4*64];    // 20 KB
__device__ uint4 g_w1q[4*4*64];    // 16 KB
__device__ uint4 g_w2q[4*4*128];   // 32 KB

// ---------------- setup: split all weights once ------------------------------
__global__ void wsplit_kernel(const float* __restrict__ W0,
                              const float* __restrict__ W1,
                              const float* __restrict__ W2) {
    int i = blockIdx.x * blockDim.x + threadIdx.x;   // 0..2047
    if (i < 1280) {
        int ks = i >> 8, rem = i & 255, qq = rem >> 6, n = rem & 63;
        int cb = 8*ks + qq, cb4 = cb + 4;
        float a0 = (2*cb    < CIN0) ? W0[(2*cb)*C1 + n]    : 0.f;
        float a1 = (2*cb+1  < CIN0) ? W0[(2*cb+1)*C1 + n]  : 0.f;
        float a2 = (2*cb4   < CIN0) ? W0[(2*cb4)*C1 + n]   : 0.f;
        float a3 = (2*cb4+1 < CIN0) ? W0[(2*cb4+1)*C1 + n] : 0.f;
        uint32_t h0, l0, h1, l1;
        split2(a0, a1, h0, l0); split2(a2, a3, h1, l1);
        g_w0q[i] = make_uint4(h0, l0, h1, l1);
    }
    if (i < 1024) {
        int ks = i >> 8, rem = i & 255, qq = rem >> 6, n = rem & 63;
        int cb = 8*ks + qq, cb4 = cb + 4;
        uint32_t h0, l0, h1, l1;
        split2(W1[(2*cb)*C2 + n],  W1[(2*cb+1)*C2 + n],  h0, l0);
        split2(W1[(2*cb4)*C2 + n], W1[(2*cb4+1)*C2 + n], h1, l1);
        g_w1q[i] = make_uint4(h0, l0, h1, l1);
    }
    if (i < 2048) {
        int ks = i >> 9, rem = i & 511, qq = rem >> 7, n = rem & 127;
        int cb = 8*ks + qq, cb4 = cb + 4;
        uint32_t h0, l0, h1, l1;
        split2(W2[(2*cb)*C3 + n],  W2[(2*cb+1)*C3 + n],  h0, l0);
        split2(W2[(2*cb4)*C3 + n], W2[(2*cb4+1)*C3 + n], h1, l1);
        g_w2q[i] = make_uint4(h0, l0, h1, l1);
    }
}

// ---------------- FPS: one block per batch (also zeroes stats) --------------
// packed f32x2 distance math (exact), scalar dd + fused argmax
#define FPS_T 256
#define FPS_PP (N/FPS_T)   // 16 points per thread = 8 pairs
__global__ void fps_kernel(const float* __restrict__ xyz, float* __restrict__ out) {
    extern __shared__ float sm[];
    float* sx = sm; float* sy = sm + N; float* sz = sm + 2*N;
    __shared__ ull skey[2][FPS_T/32];

    const int b = blockIdx.x;
    const int t = threadIdx.x;
    const int lane = t & 31, w = t >> 5;

    if (b == 0) {
        if (t < C1) { g_sum0[t]=0.f; g_sq0[t]=0.f; g_sum1[t]=0.f; g_sq1[t]=0.f; }
        if (t < C3) { g_sum2[t]=0.f; g_sq2[t]=0.f; }
    }

    const float* base = xyz + (size_t)b * N * 3;
    for (int i = t; i < N; i += FPS_T) {
        sx[i] = base[i*3+0]; sy[i] = base[i*3+1]; sz[i] = base[i*3+2];
    }
    __syncthreads();

    // pair jp holds indices (t + 2jp*FPS_T, t + (2jp+1)*FPS_T) — ascending
    ull px2[FPS_PP/2], py2[FPS_PP/2], pz2[FPS_PP/2];
    float dd[FPS_PP];
    #pragma unroll
    for (int jp = 0; jp < FPS_PP/2; jp++) {
        int i0 = t + (2*jp)*FPS_T, i1 = i0 + FPS_T;
        px2[jp] = pack2(sx[i0], sx[i1]);
        py2[jp] = pack2(sy[i0], sy[i1]);
        pz2[jp] = pack2(sz[i0], sz[i1]);
        dd[2*jp] = 1e10f; dd[2*jp+1] = 1e10f;
    }

    int far = 0;
    for (int k = 0; k < P; k++) {
        float fx = sx[far], fy = sy[far], fz = sz[far];
        if (t == 0) {
            size_t gk = (size_t)b*P + k;
            g_new_xyz[gk*3+0]=fx; g_new_xyz[gk*3+1]=fy; g_new_xyz[gk*3+2]=fz;
            out[OFF_NEWXYZ + gk*3+0]=fx; out[OFF_NEWXYZ + gk*3+1]=fy; out[OFF_NEWXYZ + gk*3+2]=fz;
        }
        // x - f == x + (-f) exactly in IEEE fp
        ull nfx = pk2(-fx), nfy = pk2(-fy), nfz = pk2(-fz);
        float bv = -1.f; int bi = 0x7fffffff;
        #pragma unroll
        for (int jp = 0; jp < FPS_PP/2; jp++) {
            ull dx = add2(px2[jp], nfx);
            ull dy = add2(py2[jp], nfy);
            ull dz = add2(pz2[jp], nfz);
            ull d  = add2(add2(mul2(dx,dx), mul2(dy,dy)), mul2(dz,dz));
            float dlo, dhi;
            upk(d, dlo, dhi);
            dd[2*jp]   = fminf(dd[2*jp],   dlo);
            dd[2*jp+1] = fminf(dd[2*jp+1], dhi);
            if (dd[2*jp]   > bv) { bv = dd[2*jp];   bi = t + (2*jp)*FPS_T; }
            if (dd[2*jp+1] > bv) { bv = dd[2*jp+1]; bi = t + (2*jp+1)*FPS_T; }
        }
        unsigned bvb = __float_as_uint(bv);
        unsigned mb  = __reduce_max_sync(0xffffffffu, bvb);
        unsigned bim = (bvb == mb) ? (unsigned)bi : 0x7fffffffu;
        unsigned bmin = __reduce_min_sync(0xffffffffu, bim);
        if (lane == 0) skey[k & 1][w] = ((ull)mb << 32) | (unsigned)(~bmin);
        __syncthreads();
        ull kb = skey[k & 1][0];
        #pragma unroll
        for (int q = 1; q < FPS_T/32; q++) {
            ull o = skey[k & 1][q];
            if (o > kb) kb = o;
        }
        far = (int)(~(unsigned)kb);
    }
}

// ---------------- Ball query: 64 centers per block, 8 per warp --------------
__global__ void ballq_kernel(const float* __restrict__ xyz, float* __restrict__ out) {
    extern __shared__ float sm[];
    float* sx = sm; float* sy = sm + N; float* sz = sm + 2*N;
    const int b = blockIdx.y;
    const int tid = threadIdx.x;
    const float* base = xyz + (size_t)b * N * 3;
    for (int i = tid; i < N; i += blockDim.x) {
        sx[i] = base[i*3+0]; sy[i] = base[i*3+1]; sz[i] = base[i*3+2];
    }
    __syncthreads();

    const int w = tid >> 5, lane = tid & 31;
    const float R2 = (float)(0.4 * 0.4);

    #pragma unroll 1
    for (int ci = 0; ci < 8; ci++) {
        const int p = blockIdx.x * 64 + w * 8 + ci;
        const int g = b * P + p;
        const float cx = g_new_xyz[g*3+0], cy = g_new_xyz[g*3+1], cz = g_new_xyz[g*3+2];

        int cnt = 0, first = -1;
        for (int basei = 0; basei < N; basei += 32) {
            int i = basei + lane;
            float dx = __fsub_rn(cx, sx[i]);
            float dy = __fsub_rn(cy, sy[i]);
            float dz = __fsub_rn(cz, sz[i]);
            float d2 = __fadd_rn(__fadd_rn(__fmul_rn(dx,dx), __fmul_rn(dy,dy)), __fmul_rn(dz,dz));
            bool pred = d2 < R2;
            unsigned m = __ballot_sync(0xffffffffu, pred);
            if (first < 0 && m) first = basei + __ffs(m) - 1;
            int rank = cnt + __popc(m & ((1u << lane) - 1u));
            if (pred && rank < S) {
                g_idx[g*S + rank] = i;
                out[OFF_IDX + g*S + rank] = (float)i;
            }
            cnt += __popc(m);
            if (cnt >= S) break;
        }
        int cntc = cnt < S ? cnt : S;
        if (lane >= cntc) {
            g_idx[g*S + lane] = first;
            out[OFF_IDX + g*S + lane] = (float)first;
        }
    }
}

// =============================================================================
// Convs: 4 groups per 128-thread block, one warp per group. y1/y2 in fp16
// fragment layout (half traffic). conv2 fully fragment-resident.
// =============================================================================

// ---------------- conv1: gather + (67->64), K padded to 80 (5 k-steps) ------
// smem: zbuf @0 (4 x 11264 = 45056), params @45056 (ssum64, ssq64) -> 45568
#define CV1_PAR  45056
#define CV1_SMEM 45568

__global__ __launch_bounds__(128, 4) void conv1_mma(const float* __restrict__ xyz,
                                                    const float* __restrict__ pts) {
    extern __shared__ char smraw[];
    float* ssum = (float*)(smraw + CV1_PAR);
    float* ssq  = ssum + 64;

    const int tid = threadIdx.x, wid = tid >> 5, lane = tid & 31;
    const int q = lane & 3, r0 = lane >> 2;
    const int g = blockIdx.x * 4 + wid;
    const int b = g >> 10;

    if (tid < 64) { ssum[tid] = 0.f; ssq[tid] = 0.f; }
    __syncthreads();

    uint32_t* zhi = (uint32_t*)smraw + wid*2816;   // [32][44] words
    uint32_t* zlo = zhi + 1408;

    {   // stage A: coalesced gather. Half-warp loads one sample row per pass.
        const int j = g_idx[g*S + lane];           // own sample index
        const float* xr = xyz + ((size_t)b*N + j)*3;
        float rx = xr[0] - g_new_xyz[g*3+0];
        float ry = xr[1] - g_new_xyz[g*3+1];
        float rz = xr[2] - g_new_xyz[g*3+2];
        uint32_t hi, lo;
        split2(rx, ry, hi, lo);                    // own row kk=0
        zhi[lane*44 + 0] = hi; zlo[lane*44 + 0] = lo;
        #pragma unroll
        for (int kz = 34; kz < 40; kz++) { zhi[lane*44 + kz] = 0u; zlo[lane*44 + kz] = 0u; }

        const int half = lane >> 4;                // which row of the pair
        const int c = lane & 15;                   // float4 chunk within row
        #pragma unroll
        for (int p = 0; p < 16; p++) {
            int s = 2*p + half;
            int rowj  = __shfl_sync(0xffffffffu, j,  s);
            float rzs = __shfl_sync(0xffffffffu, rz, s);
            float4 v = __ldg((const float4*)(pts + ((size_t)b*N + rowj)*C) + c);
            float pw = __shfl_up_sync(0xffffffffu, v.w, 1, 16);
            float prev = (c == 0) ? rzs : pw;
            uint32_t h0, l0, h1, l1;
            split2(prev, v.x, h0, l0);             // channels (4c+2, 4c+3) -> kk=2c+1
            split2(v.y,  v.z, h1, l1);             // channels (4c+4, 4c+5) -> kk=2c+2
            zhi[s*44 + 2*c + 1] = h0; zhi[s*44 + 2*c + 2] = h1;
            zlo[s*44 + 2*c + 1] = l0; zlo[s*44 + 2*c + 2] = l1;
            if (c == 15) {                         // channel 66 -> kk=33 (pad hi)
                uint32_t h2, l2;
                split2(v.w, 0.f, h2, l2);
                zhi[s*44 + 33] = h2; zlo[s*44 + 33] = l2;
            }
        }
    }
    __syncwarp();

    float acc[2][8][4];
    #pragma unroll
    for (int mt = 0; mt < 2; mt++)
        #pragma unroll
        for (int nt = 0; nt < 8; nt++)
            #pragma unroll
            for (int e = 0; e < 4; e++) acc[mt][nt][e] = 0.f;

    const int rl = lane & 15, lc = lane >> 4;
    const uint32_t smb = smem_u32(smraw);
    const uint32_t aHi = smb + (uint32_t)(wid*2816 + rl*44 + lc*4)*4;
    const uint32_t aLo = aHi + 1408u*4;

    #pragma unroll
    for (int ks = 0; ks < 5; ks++) {
        uint32_t ah[2][4], al[2][4];
        ldsm4(ah[0], aHi + ks*32);
        ldsm4(ah[1], aHi + 2816 + ks*32);     // +16 rows * 44 words * 4B
        ldsm4(al[0], aLo + ks*32);
        ldsm4(al[1], aLo + 2816 + ks*32);
        #pragma unroll
        for (int nt = 0; nt < 8; nt++) {
            uint4 wv = __ldg(&g_w0q[(ks*4 + q)*64 + 8*nt + r0]);
            #pragma unroll
            for (int mt = 0; mt < 2; mt++) {
                mma_bf16(acc[mt][nt], ah[mt], wv.x, wv.z);
                mma_bf16(acc[mt][nt], ah[mt], wv.y, wv.w);
                mma_bf16(acc[mt][nt], al[mt], wv.x, wv.z);
            }
        }
    }

    // y1 fragment store: fp16-packed uint2 per (mt,nt) per lane
    uint2* yf = g_y1h + (size_t)g*512 + lane;
    #pragma unroll
    for (int mt = 0; mt < 2; mt++)
        #pragma unroll
        for (int nt = 0; nt < 8; nt++)
            yf[(mt*8+nt)*32] = pack_h4(acc[mt][nt][0], acc[mt][nt][1],
                                       acc[mt][nt][2], acc[mt][nt][3]);

    // fragment-space stats (exact fp32 accs)
    #pragma unroll
    for (int nt = 0; nt < 8; nt++) {
        float v00 = acc[0][nt][0], v01 = acc[0][nt][1], v02 = acc[0][nt][2], v03 = acc[0][nt][3];
        float v10 = acc[1][nt][0], v11 = acc[1][nt][1], v12 = acc[1][nt][2], v13 = acc[1][nt][3];
        float s0 = v00 + v02 + v10 + v12;
        float s1 = v01 + v03 + v11 + v13;
        float q0 = v00*v00 + v02*v02 + v10*v10 + v12*v12;
        float q1 = v01*v01 + v03*v03 + v11*v11 + v13*v13;
        #pragma unroll
        for (int off = 4; off < 32; off <<= 1) {
            s0 += __shfl_xor_sync(0xffffffffu, s0, off);
            s1 += __shfl_xor_sync(0xffffffffu, s1, off);
            q0 += __shfl_xor_sync(0xffffffffu, q0, off);
            q1 += __shfl_xor_sync(0xffffffffu, q1, off);
        }
        if (r0 == 0) {
            int cc = 8*nt + 2*q;
            atomicAdd(&ssum[cc],   s0); atomicAdd(&ssum[cc+1], s1);
            atomicAdd(&ssq[cc],    q0); atomicAdd(&ssq[cc+1],  q1);
        }
    }
    __syncthreads();
    if (tid < 64) {
        atomicAdd(&g_sum0[tid], ssum[tid]);
        atomicAdd(&g_sq0[tid],  ssq[tid]);
    }
}

// ---------------- conv2: bn0+relu, [32x64]@[64x64], fully fragment-resident -
__global__ __launch_bounds__(128, 4) void conv2_mma(const float* __restrict__ g0p,
                                                    const float* __restrict__ be0) {
    __shared__ float ssc[64], ssh[64], ssum[64], ssq[64];

    const int tid = threadIdx.x, wid = tid >> 5, lane = tid & 31;
    const int q = lane & 3, r0 = lane >> 2;
    const int g = blockIdx.x * 4 + wid;

    if (tid < 64) {
        const float inv = 1.0f / (float)CNT;
        float m = g_sum0[tid] * inv;
        float v = g_sq0[tid] * inv - m*m;
        float sc = g0p[tid] * rsqrtf(v + 0.001f);
        ssc[tid] = sc; ssh[tid] = be0[tid] - m*sc;
        ssum[tid] = 0.f; ssq[tid] = 0.f;
    }
    __syncthreads();

    const uint2* xf = g_y1h + (size_t)g*512 + lane;

    float acc[2][8][4];
    #pragma unroll
    for (int mt = 0; mt < 2; mt++)
        #pragma unroll
        for (int nt = 0; nt < 8; nt++)
            #pragma unroll
            for (int e = 0; e < 4; e++) acc[mt][nt][e] = 0.f;

    #pragma unroll
    for (int ks = 0; ks < 4; ks++) {
        uint32_t ah[2][4], al[2][4];
        #pragma unroll
        for (int ts = 0; ts < 2; ts++) {
            int t = 2*ks + ts;
            float2 sc2 = *(const float2*)&ssc[8*t + 2*q];
            float2 sh2 = *(const float2*)&ssh[8*t + 2*q];
            #pragma unroll
            for (int mt = 0; mt < 2; mt++) {
                uint2 hv = __ldg(&xf[(mt*8 + t)*32]);
                float vx, vy, vz, vw;
                unpack_h4(hv, vx, vy, vz, vw);
                float z0 = fmaxf(fmaf(vx, sc2.x, sh2.x), 0.f);
                float z1 = fmaxf(fmaf(vy, sc2.y, sh2.y), 0.f);
                float z2 = fmaxf(fmaf(vz, sc2.x, sh2.x), 0.f);
                float z3 = fmaxf(fmaf(vw, sc2.y, sh2.y), 0.f);
                split2(z0, z1, ah[mt][2*ts+0], al[mt][2*ts+0]);
                split2(z2, z3, ah[mt][2*ts+1], al[mt][2*ts+1]);
            }
        }
        #pragma unroll
        for (int nt = 0; nt < 8; nt++) {
            uint4 wv = __ldg(&g_w1q[(ks*4 + q)*64 + 8*nt + r0]);
            #pragma unroll
            for (int mt = 0; mt < 2; mt++) {
                mma_bf16(acc[mt][nt], ah[mt], wv.x, wv.z);
                mma_bf16(acc[mt][nt], ah[mt], wv.y, wv.w);
                mma_bf16(acc[mt][nt], al[mt], wv.x, wv.z);
            }
        }
    }

    uint2* yf = g_y2h + (size_t)g*512 + lane;
    #pragma unroll
    for (int mt = 0; mt < 2; mt++)
        #pragma unroll
        for (int nt = 0; nt < 8; nt++)
            yf[(mt*8+nt)*32] = pack_h4(acc[mt][nt][0], acc[mt][nt][1],
                                       acc[mt][nt][2], acc[mt][nt][3]);

    #pragma unroll
    for (int nt = 0; nt < 8; nt++) {
        float v00 = acc[0][nt][0], v01 = acc[0][nt][1], v02 = acc[0][nt][2], v03 = acc[0][nt][3];
        float v10 = acc[1][nt][0], v11 = acc[1][nt][1], v12 = acc[1][nt][2], v13 = acc[1][nt][3];
        float s0 = v00 + v02 + v10 + v12;
        float s1 = v01 + v03 + v11 + v13;
        float q0 = v00*v00 + v02*v02 + v10*v10 + v12*v12;
        float q1 = v01*v01 + v03*v03 + v11*v11 + v13*v13;
        #pragma unroll
        for (int off = 4; off < 32; off <<= 1) {
            s0 += __shfl_xor_sync(0xffffffffu, s0, off);
            s1 += __shfl_xor_sync(0xffffffffu, s1, off);
            q0 += __shfl_xor_sync(0xffffffffu, q0, off);
            q1 += __shfl_xor_sync(0xffffffffu, q1, off);
        }
        if (r0 == 0) {
            int cc = 8*nt + 2*q;
            atomicAdd(&ssum[cc],   s0); atomicAdd(&ssum[cc+1], s1);
            atomicAdd(&ssq[cc],    q0); atomicAdd(&ssq[cc+1],  q1);
        }
    }
    __syncthreads();
    if (tid < 64) {
        atomicAdd(&g_sum1[tid], ssum[tid]);
        atomicAdd(&g_sq1[tid],  ssq[tid]);
    }
}

// ---------------- conv3: bn1+relu, [32x64]@[64x128] + stats + max -----------
// smem: zbuf @0 (36864), params @36864 (ssc64, ssh64, ssum128, ssq128) -> 38400
#define CV3_PAR  36864
#define CV3_SMEM 38400

__global__ __launch_bounds__(128, 4) void conv3_mma(const float* __restrict__ g1p,
                                                    const float* __restrict__ be1) {
    extern __shared__ char smraw[];
    float* ssc   = (float*)(smraw + CV3_PAR);
    float* ssh   = ssc + 64;
    float* ssum2 = ssh + 64;    // [128]
    float* ssq2  = ssum2 + 128; // [128]

    const int tid = threadIdx.x, wid = tid >> 5, lane = tid & 31;
    const int q = lane & 3, r0 = lane >> 2;
    const int g = blockIdx.x * 4 + wid;

    if (tid < 64) {
        const float inv = 1.0f / (float)CNT;
        float m = g_sum1[tid] * inv;
        float v = g_sq1[tid] * inv - m*m;
        float sc = g1p[tid] * rsqrtf(v + 0.001f);
        ssc[tid] = sc; ssh[tid] = be1[tid] - m*sc;
    }
    ssum2[tid] = 0.f; ssq2[tid] = 0.f;
    __syncthreads();

    uint32_t* zhi = (uint32_t*)smraw + wid*2304;   // [32][36] words
    uint32_t* zlo = zhi + 1152;

    {   // stage A from y2 fp16 FRAGMENT layout -> ldmatrix layout in smem
        const uint2* xf = g_y2h + (size_t)g*512 + lane;
        #pragma unroll
        for (int t = 0; t < 8; t++) {
            float2 sc2 = *(const float2*)&ssc[8*t + 2*q];
            float2 sh2 = *(const float2*)&ssh[8*t + 2*q];
            #pragma unroll
            for (int mt = 0; mt < 2; mt++) {
                uint2 hv = __ldg(&xf[(mt*8 + t)*32]);
                float vx, vy, vz, vw;
                unpack_h4(hv, vx, vy, vz, vw);
                float z0 = fmaxf(fmaf(vx, sc2.x, sh2.x), 0.f);
                float z1 = fmaxf(fmaf(vy, sc2.y, sh2.y), 0.f);
                float z2 = fmaxf(fmaf(vz, sc2.x, sh2.x), 0.f);
                float z3 = fmaxf(fmaf(vw, sc2.y, sh2.y), 0.f);
                uint32_t h0, l0, h1, l1;
                split2(z0, z1, h0, l0); split2(z2, z3, h1, l1);
                int row0 = mt*16 + r0, row1 = row0 + 8;
                zhi[row0*36 + 4*t + q] = h0; zhi[row1*36 + 4*t + q] = h1;
                zlo[row0*36 + 4*t + q] = l0; zlo[row1*36 + 4*t + q] = l1;
            }
        }
    }
    __syncwarp();

    const int rl = lane & 15, lc = lane >> 4;
    const uint32_t smb = smem_u32(smraw);
    const uint32_t aHi = smb + (uint32_t)(wid*2304 + rl*36 + lc*4)*4;
    const uint32_t aLo = aHi + 1152u*4;

    #pragma unroll 1
    for (int chn = 0; chn < 4; chn++) {       // 4 n-chunks of 32 cols
        float acc[2][4][4];
        #pragma unroll
        for (int mt = 0; mt < 2; mt++)
            #pragma unroll
            for (int ntl = 0; ntl < 4; ntl++)
                #pragma unroll
                for (int e = 0; e < 4; e++) acc[mt][ntl][e] = 0.f;

        #pragma unroll
        for (int ks = 0; ks < 4; ks++) {
            uint32_t ah[2][4], al[2][4];
            ldsm4(ah[0], aHi + ks*32);
            ldsm4(ah[1], aHi + 2304 + ks*32);
            ldsm4(al[0], aLo + ks*32);
            ldsm4(al[1], aLo + 2304 + ks*32);
            #pragma unroll
            for (int ntl = 0; ntl < 4; ntl++) {
                int nt = chn*4 + ntl;
                uint4 wv = __ldg(&g_w2q[(ks*4 + q)*128 + 8*nt + r0]);
                #pragma unroll
                for (int mt = 0; mt < 2; mt++) {
                    mma_bf16(acc[mt][ntl], ah[mt], wv.x, wv.z);
                    mma_bf16(acc[mt][ntl], ah[mt], wv.y, wv.w);
                    mma_bf16(acc[mt][ntl], al[mt], wv.x, wv.z);
                }
            }
        }

        #pragma unroll
        for (int ntl = 0; ntl < 4; ntl++) {
            int nt = chn*4 + ntl;
            float v00 = acc[0][ntl][0], v02 = acc[0][ntl][2];
            float v10 = acc[1][ntl][0], v12 = acc[1][ntl][2];
            float v01 = acc[0][ntl][1], v03 = acc[0][ntl][3];
            float v11 = acc[1][ntl][1], v13 = acc[1][ntl][3];
            float s0 = v00 + v02 + v10 + v12;
            float s1 = v01 + v03 + v11 + v13;
            float q0 = v00*v00 + v02*v02 + v10*v10 + v12*v12;
            float q1 = v01*v01 + v03*v03 + v11*v11 + v13*v13;
            float m0 = fmaxf(fmaxf(v00, v02), fmaxf(v10, v12));
            float m1 = fmaxf(fmaxf(v01, v03), fmaxf(v11, v13));
            #pragma unroll
            for (int off = 4; off < 32; off <<= 1) {
                s0 += __shfl_xor_sync(0xffffffffu, s0, off);
                s1 += __shfl_xor_sync(0xffffffffu, s1, off);
                q0 += __shfl_xor_sync(0xffffffffu, q0, off);
                q1 += __shfl_xor_sync(0xffffffffu, q1, off);
                m0 = fmaxf(m0, __shfl_xor_sync(0xffffffffu, m0, off));
                m1 = fmaxf(m1, __shfl_xor_sync(0xffffffffu, m1, off));
            }
            if (r0 == 0) {   // lanes 0..3
                int c = 8*nt + 2*q;
                atomicAdd(&ssum2[c],   s0); atomicAdd(&ssum2[c+1], s1);
                atomicAdd(&ssq2[c],    q0); atomicAdd(&ssq2[c+1],  q1);
                g_max3[(size_t)g*C3 + c]     = m0;
                g_max3[(size_t)g*C3 + c + 1] = m1;
            }
        }
    }
    __syncthreads();
    atomicAdd(&g_sum2[tid], ssum2[tid]);
    atomicAdd(&g_sq2[tid],  ssq2[tid]);
}

// ---------------- finalize: bn2 + relu on pooled maxes ----------------------
__global__ void finalize_kernel(const float* __restrict__ g2,
                                const float* __restrict__ be2,
                                float* __restrict__ out) {
    __shared__ float sc[C3], sh[C3];
    const int tid = threadIdx.x;
    if (tid < C3) {
        const float inv = 1.0f / (float)CNT;
        float m = g_sum2[tid] * inv;
        float v = g_sq2[tid] * inv - m*m;
        float s = g2[tid] * rsqrtf(v + 0.001f);
        sc[tid] = s; sh[tid] = be2[tid] - m*s;
    }
    __syncthreads();
    for (int i = blockIdx.x * blockDim.x + tid; i < B*P*C3; i += gridDim.x * blockDim.x) {
        int o = i & 127;
        out[OFF_NEWPTS + i] = fmaxf(fmaf(g_max3[i], sc[o], sh[o]), 0.f);
    }
}

// ---------------- launch -----------------------------------------------------
extern "C" void kernel_launch(void* const* d_in, const int* in_sizes, int n_in,
                              void* d_out, int out_size) {
    const float* xyz = (const float*)d_in[0];
    const float* pts = (const float*)d_in[1];
    const float* W0  = (const float*)d_in[2];
    const float* g0  = (const float*)d_in[4];
    const float* be0 = (const float*)d_in[5];
    const float* W1  = (const float*)d_in[6];
    const float* g1  = (const float*)d_in[8];
    const float* be1 = (const float*)d_in[9];
    const float* W2  = (const float*)d_in[10];
    const float* g2  = (const float*)d_in[12];
    const float* be2 = (const float*)d_in[13];
    float* out = (float*)d_out;

    const int smemPts = 3 * N * (int)sizeof(float);   // 49152
    cudaFuncSetAttribute(fps_kernel,   cudaFuncAttributeMaxDynamicSharedMemorySize, smemPts);
    cudaFuncSetAttribute(ballq_kernel, cudaFuncAttributeMaxDynamicSharedMemorySize, smemPts);
    cudaFuncSetAttribute(conv1_mma, cudaFuncAttributeMaxDynamicSharedMemorySize, CV1_SMEM);
    cudaFuncSetAttribute(conv3_mma, cudaFuncAttributeMaxDynamicSharedMemorySize, CV3_SMEM);

    wsplit_kernel<<<8, 256>>>(W0, W1, W2);
    fps_kernel<<<B, FPS_T, smemPts>>>(xyz, out);
    ballq_kernel<<<dim3(16, B), 256, smemPts>>>(xyz, out);
    conv1_mma<<<(B*P)/4, 128, CV1_SMEM>>>(xyz, pts);
    conv2_mma<<<(B*P)/4, 128>>>(g0, be0);
    conv3_mma<<<(B*P)/4, 128, CV3_SMEM>>>(g1, be1);
    finalize_kernel<<<2048, 256>>>(g2, be2, out);
}

// round 16
// speedup vs baseline: 1.0885x; 1.0885x over previous
#include <cuda_runtime.h>
#include <cuda_bf16.h>
#include <cuda_fp16.h>
#include <cstdint>

#define B 16
#define N 4096
#define C 64
#define P 1024      // NPOINT
#define S 32        // NSAMPLE
#define CIN0 67
#define C1 64
#define C2 64
#define C3 128
#define CNT (B*P*S) // 524288 samples per channel for BN

#define OFF_NEWXYZ 0
#define OFF_NEWPTS (B*P*3)                 // 49152
#define OFF_IDX    (B*P*3 + B*P*C3)        // 2146304

typedef unsigned long long ull;

// ---------------- mma.sync bf16 (baseline sm_80+ PTX, works on sm_103) -------
__device__ __forceinline__ void mma_bf16(float* d, const uint32_t* a, uint32_t b0, uint32_t b1) {
    asm volatile("mma.sync.aligned.m16n8k16.row.col.f32.bf16.bf16.f32 "
        "{%0,%1,%2,%3}, {%4,%5,%6,%7}, {%8,%9}, {%0,%1,%2,%3};"
        : "+f"(d[0]), "+f"(d[1]), "+f"(d[2]), "+f"(d[3])
        : "r"(a[0]), "r"(a[1]), "r"(a[2]), "r"(a[3]), "r"(b0), "r"(b1));
}

// ldmatrix x4: loads a full m16k16 bf16 A tile (4 m8n8 matrices) in one instr
__device__ __forceinline__ void ldsm4(uint32_t* r, uint32_t saddr) {
    asm volatile("ldmatrix.sync.aligned.m8n8.x4.shared.b16 {%0,%1,%2,%3}, [%4];"
        : "=r"(r[0]), "=r"(r[1]), "=r"(r[2]), "=r"(r[3]) : "r"(saddr));
}

__device__ __forceinline__ uint32_t smem_u32(const void* p) {
    uint32_t a;
    asm("{ .reg .u64 t; cvta.to.shared.u64 t, %1; cvt.u32.u64 %0, t; }" : "=r"(a) : "l"(p));
    return a;
}

// split fp32 pair into bf16x2 (hi) and bf16x2 (residual lo); first arg = low half
__device__ __forceinline__ void split2(float a, float b, uint32_t& hi, uint32_t& lo) {
    __nv_bfloat16 ha = __float2bfloat16_rn(a);
    __nv_bfloat16 hb = __float2bfloat16_rn(b);
    __nv_bfloat162 hh = __halves2bfloat162(ha, hb);
    hi = *reinterpret_cast<uint32_t*>(&hh);
    float la = a - __bfloat162float(ha);
    float lb = b - __bfloat162float(hb);
    __nv_bfloat162 ll = __floats2bfloat162_rn(la, lb);
    lo = *reinterpret_cast<uint32_t*>(&ll);
}

// pack 4 floats -> 2 half2 (uint2); unpack back
__device__ __forceinline__ uint2 pack_h4(float a, float b, float c, float d) {
    __half2 p0 = __floats2half2_rn(a, b);
    __half2 p1 = __floats2half2_rn(c, d);
    uint2 r;
    r.x = *reinterpret_cast<uint32_t*>(&p0);
    r.y = *reinterpret_cast<uint32_t*>(&p1);
    return r;
}
__device__ __forceinline__ void unpack_h4(uint2 v, float& a, float& b, float& c, float& d) {
    __half2 p0 = *reinterpret_cast<__half2*>(&v.x);
    __half2 p1 = *reinterpret_cast<__half2*>(&v.y);
    float2 f0 = __half22float2(p0);
    float2 f1 = __half22float2(p1);
    a = f0.x; b = f0.y; c = f1.x; d = f1.y;
}

// ---------------- scratch (static device memory; no allocations) ------------
__device__ float g_new_xyz[B*P*3];
__device__ int   g_idx[B*P*S];
// y1/y2 in MMA FRAGMENT layout, fp16-packed: per group, 16 tiles (mt*8+nt),
// each tile = 32 lanes x uint2 {h2(c0,c1), h2(c2,c3)}. index: g*512 + tile*32 + lane
__device__ uint2 g_y1h[(size_t)B*P*512];   // 67 MB
__device__ uint2 g_y2h[(size_t)B*P*512];   // 67 MB
__device__ float g_max3[(size_t)B*P*C3];   // 8 MB

__device__ float g_sum0[C1], g_sq0[C1];
__device__ float g_sum1[C2], g_sq1[C2];
__device__ float g_sum2[C3], g_sq2[C3];

// paired pre-split weight tables: entry {hi_cb, lo_cb, hi_cb+4, lo_cb+4}
// index: (ks*4 + q)*Cout + n  where cb = 8*ks + q
__device__ uint4 g_w0q[5*4*64];    // 20 KB
__device__ uint4 g_w1q[4*4*64];    // 16 KB
__device__ uint4 g_w2q[4*4*128];   // 32 KB

// ---------------- setup: split all weights once ------------------------------
__global__ void wsplit_kernel(const float* __restrict__ W0,
                              const float* __restrict__ W1,
                              const float* __restrict__ W2) {
    int i = blockIdx.x * blockDim.x + threadIdx.x;   // 0..2047
    if (i < 1280) {
        int ks = i >> 8, rem = i & 255, qq = rem >> 6, n = rem & 63;
        int cb = 8*ks + qq, cb4 = cb + 4;
        float a0 = (2*cb    < CIN0) ? W0[(2*cb)*C1 + n]    : 0.f;
        float a1 = (2*cb+1  < CIN0) ? W0[(2*cb+1)*C1 + n]  : 0.f;
        float a2 = (2*cb4   < CIN0) ? W0[(2*cb4)*C1 + n]   : 0.f;
        float a3 = (2*cb4+1 < CIN0) ? W0[(2*cb4+1)*C1 + n] : 0.f;
        uint32_t h0, l0, h1, l1;
        split2(a0, a1, h0, l0); split2(a2, a3, h1, l1);
        g_w0q[i] = make_uint4(h0, l0, h1, l1);
    }
    if (i < 1024) {
        int ks = i >> 8, rem = i & 255, qq = rem >> 6, n = rem & 63;
        int cb = 8*ks + qq, cb4 = cb + 4;
        uint32_t h0, l0, h1, l1;
        split2(W1[(2*cb)*C2 + n],  W1[(2*cb+1)*C2 + n],  h0, l0);
        split2(W1[(2*cb4)*C2 + n], W1[(2*cb4+1)*C2 + n], h1, l1);
        g_w1q[i] = make_uint4(h0, l0, h1, l1);
    }
    if (i < 2048) {
        int ks = i >> 9, rem = i & 511, qq = rem >> 7, n = rem & 127;
        int cb = 8*ks + qq, cb4 = cb + 4;
        uint32_t h0, l0, h1, l1;
        split2(W2[(2*cb)*C3 + n],  W2[(2*cb+1)*C3 + n],  h0, l0);
        split2(W2[(2*cb4)*C3 + n], W2[(2*cb4+1)*C3 + n], h1, l1);
        g_w2q[i] = make_uint4(h0, l0, h1, l1);
    }
}

// ---------------- FPS: one block per batch (also zeroes stats) --------------
// R14-proven scalar exact math
#define FPS_T 256
#define FPS_PP (N/FPS_T)   // 16 points per thread
__global__ void fps_kernel(const float* __restrict__ xyz, float* __restrict__ out) {
    extern __shared__ float sm[];
    float* sx = sm; float* sy = sm + N; float* sz = sm + 2*N;
    __shared__ ull skey[2][FPS_T/32];

    const int b = blockIdx.x;
    const int t = threadIdx.x;
    const int lane = t & 31, w = t >> 5;

    if (b == 0) {
        if (t < C1) { g_sum0[t]=0.f; g_sq0[t]=0.f; g_sum1[t]=0.f; g_sq1[t]=0.f; }
        if (t < C3) { g_sum2[t]=0.f; g_sq2[t]=0.f; }
    }

    const float* base = xyz + (size_t)b * N * 3;
    for (int i = t; i < N; i += FPS_T) {
        sx[i] = base[i*3+0]; sy[i] = base[i*3+1]; sz[i] = base[i*3+2];
    }
    __syncthreads();

    float px[FPS_PP], py[FPS_PP], pz[FPS_PP], dd[FPS_PP];
    #pragma unroll
    for (int j = 0; j < FPS_PP; j++) {
        int i = t + j*FPS_T;
        px[j]=sx[i]; py[j]=sy[i]; pz[j]=sz[i]; dd[j]=1e10f;
    }

    int far = 0;
    for (int k = 0; k < P; k++) {
        float fx = sx[far], fy = sy[far], fz = sz[far];
        if (t == 0) {
            size_t gk = (size_t)b*P + k;
            g_new_xyz[gk*3+0]=fx; g_new_xyz[gk*3+1]=fy; g_new_xyz[gk*3+2]=fz;
            out[OFF_NEWXYZ + gk*3+0]=fx; out[OFF_NEWXYZ + gk*3+1]=fy; out[OFF_NEWXYZ + gk*3+2]=fz;
        }
        float bv = -1.f; int bi = 0x7fffffff;
        #pragma unroll
        for (int j = 0; j < FPS_PP; j++) {
            float dx = __fsub_rn(px[j], fx);
            float dy = __fsub_rn(py[j], fy);
            float dz = __fsub_rn(pz[j], fz);
            float d  = __fadd_rn(__fadd_rn(__fmul_rn(dx,dx), __fmul_rn(dy,dy)), __fmul_rn(dz,dz));
            dd[j] = fminf(dd[j], d);
            if (dd[j] > bv) { bv = dd[j]; bi = t + j*FPS_T; }
        }
        unsigned bvb = __float_as_uint(bv);
        unsigned mb  = __reduce_max_sync(0xffffffffu, bvb);
        unsigned bim = (bvb == mb) ? (unsigned)bi : 0x7fffffffu;
        unsigned bmin = __reduce_min_sync(0xffffffffu, bim);
        if (lane == 0) skey[k & 1][w] = ((ull)mb << 32) | (unsigned)(~bmin);
        __syncthreads();
        ull kb = skey[k & 1][0];
        #pragma unroll
        for (int q = 1; q < FPS_T/32; q++) {
            ull o = skey[k & 1][q];
            if (o > kb) kb = o;
        }
        far = (int)(~(unsigned)kb);
    }
}

// ---------------- Ball query: 64 centers per block, 8 per warp --------------
__global__ void ballq_kernel(const float* __restrict__ xyz, float* __restrict__ out) {
    extern __shared__ float sm[];
    float* sx = sm; float* sy = sm + N; float* sz = sm + 2*N;
    const int b = blockIdx.y;
    const int tid = threadIdx.x;
    const float* base = xyz + (size_t)b * N * 3;
    for (int i = tid; i < N; i += blockDim.x) {
        sx[i] = base[i*3+0]; sy[i] = base[i*3+1]; sz[i] = base[i*3+2];
    }
    __syncthreads();

    const int w = tid >> 5, lane = tid & 31;
    const float R2 = (float)(0.4 * 0.4);

    #pragma unroll 1
    for (int ci = 0; ci < 8; ci++) {
        const int p = blockIdx.x * 64 + w * 8 + ci;
        const int g = b * P + p;
        const float cx = g_new_xyz[g*3+0], cy = g_new_xyz[g*3+1], cz = g_new_xyz[g*3+2];

        int cnt = 0, first = -1;
        for (int basei = 0; basei < N; basei += 32) {
            int i = basei + lane;
            float dx = __fsub_rn(cx, sx[i]);
            float dy = __fsub_rn(cy, sy[i]);
            float dz = __fsub_rn(cz, sz[i]);
            float d2 = __fadd_rn(__fadd_rn(__fmul_rn(dx,dx), __fmul_rn(dy,dy)), __fmul_rn(dz,dz));
            bool pred = d2 < R2;
            unsigned m = __ballot_sync(0xffffffffu, pred);
            if (first < 0 && m) first = basei + __ffs(m) - 1;
            int rank = cnt + __popc(m & ((1u << lane) - 1u));
            if (pred && rank < S) {
                g_idx[g*S + rank] = i;
                out[OFF_IDX + g*S + rank] = (float)i;
            }
            cnt += __popc(m);
            if (cnt >= S) break;
        }
        int cntc = cnt < S ? cnt : S;
        if (lane >= cntc) {
            g_idx[g*S + lane] = first;
            out[OFF_IDX + g*S + lane] = (float)first;
        }
    }
}

// =============================================================================
// Convs: 4 groups per 128-thread block, one warp per group. y1/y2 in fp16
// fragment layout (half traffic). conv2 fully fragment-resident.
// =============================================================================

// ---------------- conv1: gather + (67->64), K padded to 80 (5 k-steps) ------
// smem: zbuf @0 (4 x 11264 = 45056), params @45056 (ssum64, ssq64) -> 45568
#define CV1_PAR  45056
#define CV1_SMEM 45568

__global__ __launch_bounds__(128, 4) void conv1_mma(const float* __restrict__ xyz,
                                                    const float* __restrict__ pts) {
    extern __shared__ char smraw[];
    float* ssum = (float*)(smraw + CV1_PAR);
    float* ssq  = ssum + 64;

    const int tid = threadIdx.x, wid = tid >> 5, lane = tid & 31;
    const int q = lane & 3, r0 = lane >> 2;
    const int g = blockIdx.x * 4 + wid;
    const int b = g >> 10;

    if (tid < 64) { ssum[tid] = 0.f; ssq[tid] = 0.f; }
    __syncthreads();

    uint32_t* zhi = (uint32_t*)smraw + wid*2816;   // [32][44] words
    uint32_t* zlo = zhi + 1408;

    {   // stage A: coalesced gather. Half-warp loads one sample row per pass.
        const int j = g_idx[g*S + lane];           // own sample index
        const float* xr = xyz + ((size_t)b*N + j)*3;
        float rx = xr[0] - g_new_xyz[g*3+0];
        float ry = xr[1] - g_new_xyz[g*3+1];
        float rz = xr[2] - g_new_xyz[g*3+2];
        uint32_t hi, lo;
        split2(rx, ry, hi, lo);                    // own row kk=0
        zhi[lane*44 + 0] = hi; zlo[lane*44 + 0] = lo;
        #pragma unroll
        for (int kz = 34; kz < 40; kz++) { zhi[lane*44 + kz] = 0u; zlo[lane*44 + kz] = 0u; }

        const int half = lane >> 4;                // which row of the pair
        const int c = lane & 15;                   // float4 chunk within row
        #pragma unroll
        for (int p = 0; p < 16; p++) {
            int s = 2*p + half;
            int rowj  = __shfl_sync(0xffffffffu, j,  s);
            float rzs = __shfl_sync(0xffffffffu, rz, s);
            float4 v = __ldg((const float4*)(pts + ((size_t)b*N + rowj)*C) + c);
            float pw = __shfl_up_sync(0xffffffffu, v.w, 1, 16);
            float prev = (c == 0) ? rzs : pw;
            uint32_t h0, l0, h1, l1;
            split2(prev, v.x, h0, l0);             // channels (4c+2, 4c+3) -> kk=2c+1
            split2(v.y,  v.z, h1, l1);             // channels (4c+4, 4c+5) -> kk=2c+2
            zhi[s*44 + 2*c + 1] = h0; zhi[s*44 + 2*c + 2] = h1;
            zlo[s*44 + 2*c + 1] = l0; zlo[s*44 + 2*c + 2] = l1;
            if (c == 15) {                         // channel 66 -> kk=33 (pad hi)
                uint32_t h2, l2;
                split2(v.w, 0.f, h2, l2);
                zhi[s*44 + 33] = h2; zlo[s*44 + 33] = l2;
            }
        }
    }
    __syncwarp();

    float acc[2][8][4];
    #pragma unroll
    for (int mt = 0; mt < 2; mt++)
        #pragma unroll
        for (int nt = 0; nt < 8; nt++)
            #pragma unroll
            for (int e = 0; e < 4; e++) acc[mt][nt][e] = 0.f;

    const int rl = lane & 15, lc = lane >> 4;
    const uint32_t smb = smem_u32(smraw);
    const uint32_t aHi = smb + (uint32_t)(wid*2816 + rl*44 + lc*4)*4;
    const uint32_t aLo = aHi + 1408u*4;

    #pragma unroll
    for (int ks = 0; ks < 5; ks++) {
        uint32_t ah[2][4], al[2][4];
        ldsm4(ah[0], aHi + ks*32);
        ldsm4(ah[1], aHi + 2816 + ks*32);     // +16 rows * 44 words * 4B
        ldsm4(al[0], aLo + ks*32);
        ldsm4(al[1], aLo + 2816 + ks*32);
        #pragma unroll
        for (int nt = 0; nt < 8; nt++) {
            uint4 wv = __ldg(&g_w0q[(ks*4 + q)*64 + 8*nt + r0]);
            #pragma unroll
            for (int mt = 0; mt < 2; mt++) {
                mma_bf16(acc[mt][nt], ah[mt], wv.x, wv.z);
                mma_bf16(acc[mt][nt], ah[mt], wv.y, wv.w);
                mma_bf16(acc[mt][nt], al[mt], wv.x, wv.z);
            }
        }
    }

    // y1 fragment store: fp16-packed uint2 per (mt,nt) per lane
    uint2* yf = g_y1h + (size_t)g*512 + lane;
    #pragma unroll
    for (int mt = 0; mt < 2; mt++)
        #pragma unroll
        for (int nt = 0; nt < 8; nt++)
            yf[(mt*8+nt)*32] = pack_h4(acc[mt][nt][0], acc[mt][nt][1],
                                       acc[mt][nt][2], acc[mt][nt][3]);

    // fragment-space stats (exact fp32 accs)
    #pragma unroll
    for (int nt = 0; nt < 8; nt++) {
        float v00 = acc[0][nt][0], v01 = acc[0][nt][1], v02 = acc[0][nt][2], v03 = acc[0][nt][3];
        float v10 = acc[1][nt][0], v11 = acc[1][nt][1], v12 = acc[1][nt][2], v13 = acc[1][nt][3];
        float s0 = v00 + v02 + v10 + v12;
        float s1 = v01 + v03 + v11 + v13;
        float q0 = v00*v00 + v02*v02 + v10*v10 + v12*v12;
        float q1 = v01*v01 + v03*v03 + v11*v11 + v13*v13;
        #pragma unroll
        for (int off = 4; off < 32; off <<= 1) {
            s0 += __shfl_xor_sync(0xffffffffu, s0, off);
            s1 += __shfl_xor_sync(0xffffffffu, s1, off);
            q0 += __shfl_xor_sync(0xffffffffu, q0, off);
            q1 += __shfl_xor_sync(0xffffffffu, q1, off);
        }
        if (r0 == 0) {
            int cc = 8*nt + 2*q;
            atomicAdd(&ssum[cc],   s0); atomicAdd(&ssum[cc+1], s1);
            atomicAdd(&ssq[cc],    q0); atomicAdd(&ssq[cc+1],  q1);
        }
    }
    __syncthreads();
    if (tid < 64) {
        atomicAdd(&g_sum0[tid], ssum[tid]);
        atomicAdd(&g_sq0[tid],  ssq[tid]);
    }
}

// ---------------- conv2: bn0+relu, [32x64]@[64x64], fully fragment-resident -
__global__ __launch_bounds__(128, 4) void conv2_mma(const float* __restrict__ g0p,
                                                    const float* __restrict__ be0) {
    __shared__ float ssc[64], ssh[64], ssum[64], ssq[64];

    const int tid = threadIdx.x, wid = tid >> 5, lane = tid & 31;
    const int q = lane & 3, r0 = lane >> 2;
    const int g = blockIdx.x * 4 + wid;

    if (tid < 64) {
        const float inv = 1.0f / (float)CNT;
        float m = g_sum0[tid] * inv;
        float v = g_sq0[tid] * inv - m*m;
        float sc = g0p[tid] * rsqrtf(v + 0.001f);
        ssc[tid] = sc; ssh[tid] = be0[tid] - m*sc;
        ssum[tid] = 0.f; ssq[tid] = 0.f;
    }
    __syncthreads();

    const uint2* xf = g_y1h + (size_t)g*512 + lane;

    float acc[2][8][4];
    #pragma unroll
    for (int mt = 0; mt < 2; mt++)
        #pragma unroll
        for (int nt = 0; nt < 8; nt++)
            #pragma unroll
            for (int e = 0; e < 4; e++) acc[mt][nt][e] = 0.f;

    #pragma unroll
    for (int ks = 0; ks < 4; ks++) {
        uint32_t ah[2][4], al[2][4];
        #pragma unroll
        for (int ts = 0; ts < 2; ts++) {
            int t = 2*ks + ts;
            float2 sc2 = *(const float2*)&ssc[8*t + 2*q];
            float2 sh2 = *(const float2*)&ssh[8*t + 2*q];
            #pragma unroll
            for (int mt = 0; mt < 2; mt++) {
                uint2 hv = __ldg(&xf[(mt*8 + t)*32]);
                float vx, vy, vz, vw;
                unpack_h4(hv, vx, vy, vz, vw);
                float z0 = fmaxf(fmaf(vx, sc2.x, sh2.x), 0.f);
                float z1 = fmaxf(fmaf(vy, sc2.y, sh2.y), 0.f);
                float z2 = fmaxf(fmaf(vz, sc2.x, sh2.x), 0.f);
                float z3 = fmaxf(fmaf(vw, sc2.y, sh2.y), 0.f);
                split2(z0, z1, ah[mt][2*ts+0], al[mt][2*ts+0]);
                split2(z2, z3, ah[mt][2*ts+1], al[mt][2*ts+1]);
            }
        }
        #pragma unroll
        for (int nt = 0; nt < 8; nt++) {
            uint4 wv = __ldg(&g_w1q[(ks*4 + q)*64 + 8*nt + r0]);
            #pragma unroll
            for (int mt = 0; mt < 2; mt++) {
                mma_bf16(acc[mt][nt], ah[mt], wv.x, wv.z);
                mma_bf16(acc[mt][nt], ah[mt], wv.y, wv.w);
                mma_bf16(acc[mt][nt], al[mt], wv.x, wv.z);
            }
        }
    }

    uint2* yf = g_y2h + (size_t)g*512 + lane;
    #pragma unroll
    for (int mt = 0; mt < 2; mt++)
        #pragma unroll
        for (int nt = 0; nt < 8; nt++)
            yf[(mt*8+nt)*32] = pack_h4(acc[mt][nt][0], acc[mt][nt][1],
                                       acc[mt][nt][2], acc[mt][nt][3]);

    #pragma unroll
    for (int nt = 0; nt < 8; nt++) {
        float v00 = acc[0][nt][0], v01 = acc[0][nt][1], v02 = acc[0][nt][2], v03 = acc[0][nt][3];
        float v10 = acc[1][nt][0], v11 = acc[1][nt][1], v12 = acc[1][nt][2], v13 = acc[1][nt][3];
        float s0 = v00 + v02 + v10 + v12;
        float s1 = v01 + v03 + v11 + v13;
        float q0 = v00*v00 + v02*v02 + v10*v10 + v12*v12;
        float q1 = v01*v01 + v03*v03 + v11*v11 + v13*v13;
        #pragma unroll
        for (int off = 4; off < 32; off <<= 1) {
            s0 += __shfl_xor_sync(0xffffffffu, s0, off);
            s1 += __shfl_xor_sync(0xffffffffu, s1, off);
            q0 += __shfl_xor_sync(0xffffffffu, q0, off);
            q1 += __shfl_xor_sync(0xffffffffu, q1, off);
        }
        if (r0 == 0) {
            int cc = 8*nt + 2*q;
            atomicAdd(&ssum[cc],   s0); atomicAdd(&ssum[cc+1], s1);
            atomicAdd(&ssq[cc],    q0); atomicAdd(&ssq[cc+1],  q1);
        }
    }
    __syncthreads();
    if (tid < 64) {
        atomicAdd(&g_sum1[tid], ssum[tid]);
        atomicAdd(&g_sq1[tid],  ssq[tid]);
    }
}

// ---------------- conv3: bn1+relu, [32x64]@[64x128] + stats + max -----------
// 2 n-chunks of 64 cols (A fragments reloaded 2x instead of 4x)
// smem: zbuf @0 (36864), params @36864 (ssc64, ssh64, ssum128, ssq128) -> 38400
#define CV3_PAR  36864
#define CV3_SMEM 38400

__global__ __launch_bounds__(128, 4) void conv3_mma(const float* __restrict__ g1p,
                                                    const float* __restrict__ be1) {
    extern __shared__ char smraw[];
    float* ssc   = (float*)(smraw + CV3_PAR);
    float* ssh   = ssc + 64;
    float* ssum2 = ssh + 64;    // [128]
    float* ssq2  = ssum2 + 128; // [128]

    const int tid = threadIdx.x, wid = tid >> 5, lane = tid & 31;
    const int q = lane & 3, r0 = lane >> 2;
    const int g = blockIdx.x * 4 + wid;

    if (tid < 64) {
        const float inv = 1.0f / (float)CNT;
        float m = g_sum1[tid] * inv;
        float v = g_sq1[tid] * inv - m*m;
        float sc = g1p[tid] * rsqrtf(v + 0.001f);
        ssc[tid] = sc; ssh[tid] = be1[tid] - m*sc;
    }
    ssum2[tid] = 0.f; ssq2[tid] = 0.f;
    __syncthreads();

    uint32_t* zhi = (uint32_t*)smraw + wid*2304;   // [32][36] words
    uint32_t* zlo = zhi + 1152;

    {   // stage A from y2 fp16 FRAGMENT layout -> ldmatrix layout in smem
        const uint2* xf = g_y2h + (size_t)g*512 + lane;
        #pragma unroll
        for (int t = 0; t < 8; t++) {
            float2 sc2 = *(const float2*)&ssc[8*t + 2*q];
            float2 sh2 = *(const float2*)&ssh[8*t + 2*q];
            #pragma unroll
            for (int mt = 0; mt < 2; mt++) {
                uint2 hv = __ldg(&xf[(mt*8 + t)*32]);
                float vx, vy, vz, vw;
                unpack_h4(hv, vx, vy, vz, vw);
                float z0 = fmaxf(fmaf(vx, sc2.x, sh2.x), 0.f);
                float z1 = fmaxf(fmaf(vy, sc2.y, sh2.y), 0.f);
                float z2 = fmaxf(fmaf(vz, sc2.x, sh2.x), 0.f);
                float z3 = fmaxf(fmaf(vw, sc2.y, sh2.y), 0.f);
                uint32_t h0, l0, h1, l1;
                split2(z0, z1, h0, l0); split2(z2, z3, h1, l1);
                int row0 = mt*16 + r0, row1 = row0 + 8;
                zhi[row0*36 + 4*t + q] = h0; zhi[row1*36 + 4*t + q] = h1;
                zlo[row0*36 + 4*t + q] = l0; zlo[row1*36 + 4*t + q] = l1;
            }
        }
    }
    __syncwarp();

    const int rl = lane & 15, lc = lane >> 4;
    const uint32_t smb = smem_u32(smraw);
    const uint32_t aHi = smb + (uint32_t)(wid*2304 + rl*36 + lc*4)*4;
    const uint32_t aLo = aHi + 1152u*4;

    #pragma unroll 1
    for (int chn = 0; chn < 2; chn++) {       // 2 n-chunks of 64 cols
        float acc[2][8][4];
        #pragma unroll
        for (int mt = 0; mt < 2; mt++)
            #pragma unroll
            for (int ntl = 0; ntl < 8; ntl++)
                #pragma unroll
                for (int e = 0; e < 4; e++) acc[mt][ntl][e] = 0.f;

        #pragma unroll
        for (int ks = 0; ks < 4; ks++) {
            uint32_t ah[2][4], al[2][4];
            ldsm4(ah[0], aHi + ks*32);
            ldsm4(ah[1], aHi + 2304 + ks*32);
            ldsm4(al[0], aLo + ks*32);
            ldsm4(al[1], aLo + 2304 + ks*32);
            #pragma unroll
            for (int ntl = 0; ntl < 8; ntl++) {
                int nt = chn*8 + ntl;
                uint4 wv = __ldg(&g_w2q[(ks*4 + q)*128 + 8*nt + r0]);
                #pragma unroll
                for (int mt = 0; mt < 2; mt++) {
                    mma_bf16(acc[mt][ntl], ah[mt], wv.x, wv.z);
                    mma_bf16(acc[mt][ntl], ah[mt], wv.y, wv.w);
                    mma_bf16(acc[mt][ntl], al[mt], wv.x, wv.z);
                }
            }
        }

        #pragma unroll
        for (int ntl = 0; ntl < 8; ntl++) {
            int nt = chn*8 + ntl;
            float v00 = acc[0][ntl][0], v02 = acc[0][ntl][2];
            float v10 = acc[1][ntl][0], v12 = acc[1][ntl][2];
            float v01 = acc[0][ntl][1], v03 = acc[0][ntl][3];
            float v11 = acc[1][ntl][1], v13 = acc[1][ntl][3];
            float s0 = v00 + v02 + v10 + v12;
            float s1 = v01 + v03 + v11 + v13;
            float q0 = v00*v00 + v02*v02 + v10*v10 + v12*v12;
            float q1 = v01*v01 + v03*v03 + v11*v11 + v13*v13;
            float m0 = fmaxf(fmaxf(v00, v02), fmaxf(v10, v12));
            float m1 = fmaxf(fmaxf(v01, v03), fmaxf(v11, v13));
            #pragma unroll
            for (int off = 4; off < 32; off <<= 1) {
                s0 += __shfl_xor_sync(0xffffffffu, s0, off);
                s1 += __shfl_xor_sync(0xffffffffu, s1, off);
                q0 += __shfl_xor_sync(0xffffffffu, q0, off);
                q1 += __shfl_xor_sync(0xffffffffu, q1, off);
                m0 = fmaxf(m0, __shfl_xor_sync(0xffffffffu, m0, off));
                m1 = fmaxf(m1, __shfl_xor_sync(0xffffffffu, m1, off));
            }
            if (r0 == 0) {   // lanes 0..3
                int c = 8*nt + 2*q;
                atomicAdd(&ssum2[c],   s0); atomicAdd(&ssum2[c+1], s1);
                atomicAdd(&ssq2[c],    q0); atomicAdd(&ssq2[c+1],  q1);
                g_max3[(size_t)g*C3 + c]     = m0;
                g_max3[(size_t)g*C3 + c + 1] = m1;
            }
        }
    }
    __syncthreads();
    atomicAdd(&g_sum2[tid], ssum2[tid]);
    atomicAdd(&g_sq2[tid],  ssq2[tid]);
}

// ---------------- finalize: bn2 + relu on pooled maxes ----------------------
__global__ void finalize_kernel(const float* __restrict__ g2,
                                const float* __restrict__ be2,
                                float* __restrict__ out) {
    __shared__ float sc[C3], sh[C3];
    const int tid = threadIdx.x;
    if (tid < C3) {
        const float inv = 1.0f / (float)CNT;
        float m = g_sum2[tid] * inv;
        float v = g_sq2[tid] * inv - m*m;
        float s = g2[tid] * rsqrtf(v + 0.001f);
        sc[tid] = s; sh[tid] = be2[tid] - m*s;
    }
    __syncthreads();
    for (int i = blockIdx.x * blockDim.x + tid; i < B*P*C3; i += gridDim.x * blockDim.x) {
        int o = i & 127;
        out[OFF_NEWPTS + i] = fmaxf(fmaf(g_max3[i], sc[o], sh[o]), 0.f);
    }
}

// ---------------- launch -----------------------------------------------------
extern "C" void kernel_launch(void* const* d_in, const int* in_sizes, int n_in,
                              void* d_out, int out_size) {
    const float* xyz = (const float*)d_in[0];
    const float* pts = (const float*)d_in[1];
    const float* W0  = (const float*)d_in[2];
    const float* g0  = (const float*)d_in[4];
    const float* be0 = (const float*)d_in[5];
    const float* W1  = (const float*)d_in[6];
    const float* g1  = (const float*)d_in[8];
    const float* be1 = (const float*)d_in[9];
    const float* W2  = (const float*)d_in[10];
    const float* g2  = (const float*)d_in[12];
    const float* be2 = (const float*)d_in[13];
    float* out = (float*)d_out;

    const int smemPts = 3 * N * (int)sizeof(float);   // 49152
    cudaFuncSetAttribute(fps_kernel,   cudaFuncAttributeMaxDynamicSharedMemorySize, smemPts);
    cudaFuncSetAttribute(ballq_kernel, cudaFuncAttributeMaxDynamicSharedMemorySize, smemPts);
    cudaFuncSetAttribute(conv1_mma, cudaFuncAttributeMaxDynamicSharedMemorySize, CV1_SMEM);
    cudaFuncSetAttribute(conv3_mma, cudaFuncAttributeMaxDynamicSharedMemorySize, CV3_SMEM);

    wsplit_kernel<<<8, 256>>>(W0, W1, W2);
    fps_kernel<<<B, FPS_T, smemPts>>>(xyz, out);
    ballq_kernel<<<dim3(16, B), 256, smemPts>>>(xyz, out);
    conv1_mma<<<(B*P)/4, 128, CV1_SMEM>>>(xyz, pts);
    conv2_mma<<<(B*P)/4, 128>>>(g0, be0);
    conv3_mma<<<(B*P)/4, 128, CV3_SMEM>>>(g1, be1);
    finalize_kernel<<<2048, 256>>>(g2, be2, out);
}